// round 14
// baseline (speedup 1.0000x reference)
#include <cuda_runtime.h>
#include <cstdint>
#include <cmath>

namespace {

constexpr int kB  = 16;
constexpr int kSQ = 2048;
constexpr int kSK = 2048;
constexpr int kD  = 128;
constexpr int kDV = 128;

constexpr int BM = 64;          // query rows per CTA (16 per warp)
constexpr int BN = 32;          // keys per iteration
constexpr int NWARPS = 4;
constexpr int NTHREADS = NWARPS * 32;

constexpr int KT_Q = kD / 8;    // 16 k-tiles for S = Q K^T
constexpr int NT_S = BN / 8;    // 4 n-tiles of S
constexpr int KT_P = BN / 8;    // 4 k-tiles for O += P V
constexpr int NT_O = kDV / 8;   // 16 n-tiles of O

// padded smem strides (in 32-bit words) -> conflict-free fragment reads
constexpr int KS_STRIDE = kD + 4;    // 132
constexpr int VS_STRIDE = kDV + 8;   // 136
constexpr int PS_STRIDE = BN + 4;    // 36

constexpr float INV_SCALE  = 0.2f;          // scores * (1/SCALE_FACTOR)
constexpr float KEEP_SCALE = 1.0f / 0.9f;   // inverted-dropout scale

constexpr int MASK_ELEMS = kB * kSQ * kSK;  // 67,108,864 — unique among inputs

// mask dtype mode: 0 = uint8 bytes, 1 = int32, 2 = float32
__device__ int g_mask_mode;

__global__ void detect_mask_kernel(const uint32_t* __restrict__ m) {
    __shared__ int s_i32, s_f32;
    if (threadIdx.x == 0) { s_i32 = 0; s_f32 = 0; }
    __syncthreads();
    int ci = 0, cf = 0;
    // 16384 samples, stride 997 words: max index 16,334,851 words < 16,777,216
    // (the smallest possible buffer: 67,108,864 bytes if the mask is uint8).
    for (int i = threadIdx.x; i < 16384; i += blockDim.x) {
        uint32_t w = m[(size_t)i * 997u];
        ci += (w <= 1u) ? 1 : 0;
        cf += (w == 0u || w == 0x3F800000u) ? 1 : 0;
    }
    atomicAdd(&s_i32, ci);
    atomicAdd(&s_f32, cf);
    __syncthreads();
    if (threadIdx.x == 0) {
        int mode = 0;                      // default: raw bytes
        if (s_i32 > 16300)      mode = 1;  // words are all 0/1 -> int32
        else if (s_f32 > 16300) mode = 2;  // words are all 0.0f/1.0f -> float32
        g_mask_mode = mode;
    }
}

__device__ __forceinline__ uint32_t f2tf(float f) {
    uint32_t r;
    asm("cvt.rna.tf32.f32 %0, %1;" : "=r"(r) : "f"(f));
    return r;
}

__device__ __forceinline__ void mma_tf32(float* d,
                                         uint32_t a0, uint32_t a1, uint32_t a2, uint32_t a3,
                                         uint32_t b0, uint32_t b1) {
    asm volatile(
        "mma.sync.aligned.m16n8k8.row.col.f32.tf32.tf32.f32 "
        "{%0,%1,%2,%3}, {%4,%5,%6,%7}, {%8,%9}, {%0,%1,%2,%3};\n"
        : "+f"(d[0]), "+f"(d[1]), "+f"(d[2]), "+f"(d[3])
        : "r"(a0), "r"(a1), "r"(a2), "r"(a3), "r"(b0), "r"(b1));
}

__global__ void __launch_bounds__(NTHREADS, 2)
fa_tf32_kernel(const float* __restrict__ Q, const float* __restrict__ K,
               const float* __restrict__ V, const void* __restrict__ mask,
               float* __restrict__ O)
{
    __shared__ __align__(16) uint32_t Ks[BN * KS_STRIDE];   // tf32 K tile [key][d]
    __shared__ __align__(16) uint32_t Vs[BN * VS_STRIDE];   // tf32 V tile [key][dv]
    __shared__ __align__(16) uint32_t Ps[BM * PS_STRIDE];   // tf32 masked probs
    __shared__ __align__(16) unsigned char Ms[BM * BN];     // mask tile (bytes, 1=keep)

    const int tid  = threadIdx.x;
    const int warp = tid >> 5;
    const int lane = tid & 31;
    const int g    = lane >> 2;   // groupID (row within m16 tile)
    const int c    = lane & 3;    // threadID-in-group
    const int b    = blockIdx.y;
    const int q0   = blockIdx.x * BM;
    const int wrow = warp * 16;
    const int mode = g_mask_mode; // uniform across grid

    // ---- Q fragments, resident for the whole kernel; fold 0.2 scale in fp32 ----
    uint32_t qa[KT_Q][4];
    {
        const float* r0p = Q + ((size_t)b * kSQ + q0 + wrow + g) * kD;
        const float* r1p = r0p + 8 * (size_t)kD;
        #pragma unroll
        for (int kt = 0; kt < KT_Q; ++kt) {
            const int cb = kt * 8 + c;
            qa[kt][0] = f2tf(r0p[cb]     * INV_SCALE);
            qa[kt][1] = f2tf(r1p[cb]     * INV_SCALE);
            qa[kt][2] = f2tf(r0p[cb + 4] * INV_SCALE);
            qa[kt][3] = f2tf(r1p[cb + 4] * INV_SCALE);
        }
    }

    float o[NT_O][4];
    #pragma unroll
    for (int nt = 0; nt < NT_O; ++nt) { o[nt][0] = 0.f; o[nt][1] = 0.f; o[nt][2] = 0.f; o[nt][3] = 0.f; }
    float m0 = -INFINITY, m1 = -INFINITY;   // running row maxima (rows g, g+8)
    float l0 = 0.f, l1 = 0.f;               // running UNMASKED softmax denominators

    for (int n0 = 0; n0 < kSK; n0 += BN) {
        __syncthreads();   // previous iteration done reading Ks/Vs/Ms

        // ---- stage K tile (fp32 -> tf32) ----
        {
            const float4* src = (const float4*)(K + ((size_t)b * kSK + n0) * kD);
            #pragma unroll
            for (int i = 0; i < (BN * kD / 4) / NTHREADS; ++i) {
                const int idx = tid + i * NTHREADS;
                const int row = idx >> 5;
                const int c4  = idx & 31;
                float4 v = src[idx];
                uint4 t;
                t.x = f2tf(v.x); t.y = f2tf(v.y); t.z = f2tf(v.z); t.w = f2tf(v.w);
                *(uint4*)&Ks[row * KS_STRIDE + c4 * 4] = t;
            }
        }
        // ---- stage V tile (fp32 -> tf32) ----
        {
            const float4* src = (const float4*)(V + ((size_t)b * kSK + n0) * kDV);
            #pragma unroll
            for (int i = 0; i < (BN * kDV / 4) / NTHREADS; ++i) {
                const int idx = tid + i * NTHREADS;
                const int row = idx >> 5;
                const int c4  = idx & 31;
                float4 v = src[idx];
                uint4 t;
                t.x = f2tf(v.x); t.y = f2tf(v.y); t.z = f2tf(v.z); t.w = f2tf(v.w);
                *(uint4*)&Vs[row * VS_STRIDE + c4 * 4] = t;
            }
        }
        // ---- stage mask tile [BM][BN] -> bytes, dtype-adaptive ----
        if (mode == 0) {
            // raw bytes (bool as uint8)
            const unsigned char* mb = (const unsigned char*)mask;
            const int row  = tid >> 1;
            const int half = tid & 1;
            *(uint4*)(Ms + row * BN + half * 16) =
                *(const uint4*)(mb + ((size_t)b * kSQ + q0 + row) * kSK + n0 + half * 16);
        } else if (mode == 1) {
            // int32 0/1
            const int* mi = (const int*)mask;
            #pragma unroll
            for (int i = 0; i < (BM * BN / 4) / NTHREADS; ++i) {   // 4 int4 per thread
                const int idx = tid + i * NTHREADS;                 // 0..511 int4s
                const int row = idx >> 3;                           // 8 int4 per row
                const int c4  = idx & 7;
                int4 v = *(const int4*)(mi + ((size_t)b * kSQ + q0 + row) * kSK + n0 + c4 * 4);
                uchar4 u = make_uchar4(v.x != 0, v.y != 0, v.z != 0, v.w != 0);
                *(uchar4*)(Ms + row * BN + c4 * 4) = u;
            }
        } else {
            // float32 0.0/1.0
            const float* mf = (const float*)mask;
            #pragma unroll
            for (int i = 0; i < (BM * BN / 4) / NTHREADS; ++i) {
                const int idx = tid + i * NTHREADS;
                const int row = idx >> 3;
                const int c4  = idx & 7;
                float4 v = *(const float4*)(mf + ((size_t)b * kSQ + q0 + row) * kSK + n0 + c4 * 4);
                uchar4 u = make_uchar4(v.x != 0.f, v.y != 0.f, v.z != 0.f, v.w != 0.f);
                *(uchar4*)(Ms + row * BN + c4 * 4) = u;
            }
        }

        __syncthreads();

        // ---- S = (0.2 Q) K^T ----
        float s[NT_S][4];
        #pragma unroll
        for (int nt = 0; nt < NT_S; ++nt) { s[nt][0] = 0.f; s[nt][1] = 0.f; s[nt][2] = 0.f; s[nt][3] = 0.f; }
        #pragma unroll
        for (int kt = 0; kt < KT_Q; ++kt) {
            #pragma unroll
            for (int nt = 0; nt < NT_S; ++nt) {
                const uint32_t* kp = &Ks[(nt * 8 + g) * KS_STRIDE + kt * 8 + c];
                mma_tf32(s[nt], qa[kt][0], qa[kt][1], qa[kt][2], qa[kt][3], kp[0], kp[4]);
            }
        }

        // ---- online softmax ----
        float rmax0 = fmaxf(s[0][0], s[0][1]);
        float rmax1 = fmaxf(s[0][2], s[0][3]);
        #pragma unroll
        for (int nt = 1; nt < NT_S; ++nt) {
            rmax0 = fmaxf(rmax0, fmaxf(s[nt][0], s[nt][1]));
            rmax1 = fmaxf(rmax1, fmaxf(s[nt][2], s[nt][3]));
        }
        rmax0 = fmaxf(rmax0, __shfl_xor_sync(0xffffffffu, rmax0, 1));
        rmax0 = fmaxf(rmax0, __shfl_xor_sync(0xffffffffu, rmax0, 2));
        rmax1 = fmaxf(rmax1, __shfl_xor_sync(0xffffffffu, rmax1, 1));
        rmax1 = fmaxf(rmax1, __shfl_xor_sync(0xffffffffu, rmax1, 2));

        const float m0n = fmaxf(m0, rmax0);
        const float m1n = fmaxf(m1, rmax1);
        const float al0 = __expf(m0 - m0n);
        const float al1 = __expf(m1 - m1n);

        float ps0 = 0.f, ps1 = 0.f;
        #pragma unroll
        for (int nt = 0; nt < NT_S; ++nt) {
            const float p0 = __expf(s[nt][0] - m0n);
            const float p1 = __expf(s[nt][1] - m0n);
            const float p2 = __expf(s[nt][2] - m1n);
            const float p3 = __expf(s[nt][3] - m1n);
            ps0 += p0 + p1;                   // UNMASKED sum (reference semantics)
            ps1 += p2 + p3;

            const int col = nt * 8 + 2 * c;
            const unsigned char* mk0 = &Ms[(wrow + g)     * BN + col];
            const unsigned char* mk1 = &Ms[(wrow + g + 8) * BN + col];
            uint2 w0, w1;
            w0.x = f2tf(mk0[0] ? p0 * KEEP_SCALE : 0.f);
            w0.y = f2tf(mk0[1] ? p1 * KEEP_SCALE : 0.f);
            w1.x = f2tf(mk1[0] ? p2 * KEEP_SCALE : 0.f);
            w1.y = f2tf(mk1[1] ? p3 * KEEP_SCALE : 0.f);
            *(uint2*)&Ps[(wrow + g)     * PS_STRIDE + col] = w0;
            *(uint2*)&Ps[(wrow + g + 8) * PS_STRIDE + col] = w1;
        }
        ps0 += __shfl_xor_sync(0xffffffffu, ps0, 1);
        ps0 += __shfl_xor_sync(0xffffffffu, ps0, 2);
        ps1 += __shfl_xor_sync(0xffffffffu, ps1, 1);
        ps1 += __shfl_xor_sync(0xffffffffu, ps1, 2);

        l0 = l0 * al0 + ps0;
        l1 = l1 * al1 + ps1;
        m0 = m0n; m1 = m1n;

        #pragma unroll
        for (int nt = 0; nt < NT_O; ++nt) {
            o[nt][0] *= al0; o[nt][1] *= al0;
            o[nt][2] *= al1; o[nt][3] *= al1;
        }

        __syncwarp();   // P slice is per-warp: STS(P) before cross-lane LDS(P)

        // ---- O += P V ----
        #pragma unroll
        for (int kt = 0; kt < KT_P; ++kt) {
            const uint32_t a0 = Ps[(wrow + g)     * PS_STRIDE + kt * 8 + c];
            const uint32_t a1 = Ps[(wrow + g + 8) * PS_STRIDE + kt * 8 + c];
            const uint32_t a2 = Ps[(wrow + g)     * PS_STRIDE + kt * 8 + c + 4];
            const uint32_t a3 = Ps[(wrow + g + 8) * PS_STRIDE + kt * 8 + c + 4];
            #pragma unroll
            for (int nt = 0; nt < NT_O; ++nt) {
                const uint32_t b0 = Vs[(kt * 8 + c)     * VS_STRIDE + nt * 8 + g];
                const uint32_t b1 = Vs[(kt * 8 + c + 4) * VS_STRIDE + nt * 8 + g];
                mma_tf32(o[nt], a0, a1, a2, a3, b0, b1);
            }
        }
    }

    // ---- epilogue: normalize by UNMASKED denominator and store ----
    const float inv0 = 1.f / l0;
    const float inv1 = 1.f / l1;
    float* ob = O + ((size_t)b * kSQ + q0 + wrow) * kDV;
    #pragma unroll
    for (int nt = 0; nt < NT_O; ++nt) {
        const int col = nt * 8 + 2 * c;
        float2 v0 = make_float2(o[nt][0] * inv0, o[nt][1] * inv0);
        float2 v1 = make_float2(o[nt][2] * inv1, o[nt][3] * inv1);
        *(float2*)(ob + (size_t)g       * kDV + col) = v0;
        *(float2*)(ob + (size_t)(g + 8) * kDV + col) = v1;
    }
}

} // namespace

extern "C" void kernel_launch(void* const* d_in, const int* in_sizes, int n_in,
                              void* d_out, int out_size)
{
    (void)out_size;
    // Identify the mask by its unique element count; the remaining three
    // inputs keep their relative order (x1=Q, x2=K, x3=V) under either
    // dict or alphabetical metadata ordering.
    int midx = 3;
    for (int i = 0; i < n_in; ++i)
        if (in_sizes[i] == MASK_ELEMS) { midx = i; break; }

    const float* qkv[3] = {nullptr, nullptr, nullptr};
    int j = 0;
    for (int i = 0; i < n_in && j < 3; ++i)
        if (i != midx) qkv[j++] = (const float*)d_in[i];

    const void* mask = d_in[midx];
    float* out = (float*)d_out;

    detect_mask_kernel<<<1, 256>>>((const uint32_t*)mask);

    dim3 grid(kSQ / BM, kB);
    fa_tf32_kernel<<<grid, NTHREADS>>>(qkv[0], qkv[1], qkv[2], mask, out);
}

// round 16
// speedup vs baseline: 1.0027x; 1.0027x over previous
#include <cuda_runtime.h>
#include <cstdint>
#include <cmath>

namespace {

constexpr int kB  = 16;
constexpr int kSQ = 2048;
constexpr int kSK = 2048;
constexpr int kD  = 128;
constexpr int kDV = 128;

constexpr int BM = 64;          // query rows per CTA (16 per warp)
constexpr int BN = 32;          // keys per iteration
constexpr int NWARPS = 4;
constexpr int NTHREADS = NWARPS * 32;

constexpr int KT_Q = kD / 8;    // 16 k-tiles for S = Q K^T
constexpr int NT_S = BN / 8;    // 4 n-tiles of S
constexpr int KT_P = BN / 8;    // 4 k-tiles for O += P V
constexpr int NT_O = kDV / 8;   // 16 n-tiles of O

// padded smem strides (in 32-bit words) -> conflict-free fragment reads
constexpr int KS_STRIDE = kD + 4;    // 132
constexpr int VS_STRIDE = kDV + 8;   // 136
constexpr int PS_STRIDE = BN + 4;    // 36

constexpr float INV_SCALE  = 0.2f;          // scores * (1/SCALE_FACTOR)
constexpr float KEEP_SCALE = 1.0f / 0.9f;   // inverted-dropout scale

constexpr int MASK_ELEMS = kB * kSQ * kSK;  // 67,108,864 — unique among inputs

// mask dtype mode: 0 = uint8 bytes, 1 = int32, 2 = float32
__device__ int g_mask_mode;

__global__ void detect_mask_kernel(const uint32_t* __restrict__ m) {
    __shared__ int s_i32, s_f32;
    if (threadIdx.x == 0) { s_i32 = 0; s_f32 = 0; }
    __syncthreads();
    int ci = 0, cf = 0;
    // 16384 samples, stride 997 words: max index 16,334,851 words < 16,777,216
    // (the smallest possible buffer: 67,108,864 bytes if the mask is uint8).
    for (int i = threadIdx.x; i < 16384; i += blockDim.x) {
        uint32_t w = m[(size_t)i * 997u];
        ci += (w <= 1u) ? 1 : 0;
        cf += (w == 0u || w == 0x3F800000u) ? 1 : 0;
    }
    atomicAdd(&s_i32, ci);
    atomicAdd(&s_f32, cf);
    __syncthreads();
    if (threadIdx.x == 0) {
        int mode = 0;                      // default: raw bytes
        if (s_i32 > 16300)      mode = 1;  // words are all 0/1 -> int32
        else if (s_f32 > 16300) mode = 2;  // words are all 0.0f/1.0f -> float32
        g_mask_mode = mode;
    }
}

__device__ __forceinline__ uint32_t f2tf(float f) {
    uint32_t r;
    asm("cvt.rna.tf32.f32 %0, %1;" : "=r"(r) : "f"(f));
    return r;
}

__device__ __forceinline__ void mma_tf32(float* d,
                                         uint32_t a0, uint32_t a1, uint32_t a2, uint32_t a3,
                                         uint32_t b0, uint32_t b1) {
    asm volatile(
        "mma.sync.aligned.m16n8k8.row.col.f32.tf32.tf32.f32 "
        "{%0,%1,%2,%3}, {%4,%5,%6,%7}, {%8,%9}, {%0,%1,%2,%3};\n"
        : "+f"(d[0]), "+f"(d[1]), "+f"(d[2]), "+f"(d[3])
        : "r"(a0), "r"(a1), "r"(a2), "r"(a3), "r"(b0), "r"(b1));
}

__global__ void __launch_bounds__(NTHREADS, 2)
fa_tf32_kernel(const float* __restrict__ Q, const float* __restrict__ K,
               const float* __restrict__ V, const void* __restrict__ mask,
               float* __restrict__ O)
{
    __shared__ __align__(16) uint32_t Ks[BN * KS_STRIDE];   // tf32 K tile [key][d]
    __shared__ __align__(16) uint32_t Vs[BN * VS_STRIDE];   // tf32 V tile [key][dv]
    __shared__ __align__(16) uint32_t Ps[BM * PS_STRIDE];   // tf32 masked probs
    __shared__ __align__(16) unsigned char Ms[BM * BN];     // mask tile (bytes, 1=keep)

    const int tid  = threadIdx.x;
    const int warp = tid >> 5;
    const int lane = tid & 31;
    const int g    = lane >> 2;   // groupID (row within m16 tile)
    const int c    = lane & 3;    // threadID-in-group
    const int b    = blockIdx.y;
    const int q0   = blockIdx.x * BM;
    const int wrow = warp * 16;
    const int mode = g_mask_mode; // uniform across grid

    // ---- Q fragments, resident for the whole kernel; fold 0.2 scale in fp32 ----
    uint32_t qa[KT_Q][4];
    {
        const float* r0p = Q + ((size_t)b * kSQ + q0 + wrow + g) * kD;
        const float* r1p = r0p + 8 * (size_t)kD;
        #pragma unroll
        for (int kt = 0; kt < KT_Q; ++kt) {
            const int cb = kt * 8 + c;
            qa[kt][0] = f2tf(r0p[cb]     * INV_SCALE);
            qa[kt][1] = f2tf(r1p[cb]     * INV_SCALE);
            qa[kt][2] = f2tf(r0p[cb + 4] * INV_SCALE);
            qa[kt][3] = f2tf(r1p[cb + 4] * INV_SCALE);
        }
    }

    float o[NT_O][4];
    #pragma unroll
    for (int nt = 0; nt < NT_O; ++nt) { o[nt][0] = 0.f; o[nt][1] = 0.f; o[nt][2] = 0.f; o[nt][3] = 0.f; }
    float m0 = -INFINITY, m1 = -INFINITY;   // running row maxima (rows g, g+8)
    float l0 = 0.f, l1 = 0.f;               // running UNMASKED softmax denominators

    for (int n0 = 0; n0 < kSK; n0 += BN) {
        __syncthreads();   // previous iteration done reading Ks/Vs/Ms

        // ---- stage K tile (fp32 -> tf32) ----
        {
            const float4* src = (const float4*)(K + ((size_t)b * kSK + n0) * kD);
            #pragma unroll
            for (int i = 0; i < (BN * kD / 4) / NTHREADS; ++i) {
                const int idx = tid + i * NTHREADS;
                const int row = idx >> 5;
                const int c4  = idx & 31;
                float4 v = src[idx];
                uint4 t;
                t.x = f2tf(v.x); t.y = f2tf(v.y); t.z = f2tf(v.z); t.w = f2tf(v.w);
                *(uint4*)&Ks[row * KS_STRIDE + c4 * 4] = t;
            }
        }
        // ---- stage V tile (fp32 -> tf32) ----
        {
            const float4* src = (const float4*)(V + ((size_t)b * kSK + n0) * kDV);
            #pragma unroll
            for (int i = 0; i < (BN * kDV / 4) / NTHREADS; ++i) {
                const int idx = tid + i * NTHREADS;
                const int row = idx >> 5;
                const int c4  = idx & 31;
                float4 v = src[idx];
                uint4 t;
                t.x = f2tf(v.x); t.y = f2tf(v.y); t.z = f2tf(v.z); t.w = f2tf(v.w);
                *(uint4*)&Vs[row * VS_STRIDE + c4 * 4] = t;
            }
        }
        // ---- stage mask tile [BM][BN] -> bytes, dtype-adaptive ----
        if (mode == 0) {
            // raw bytes (bool as uint8)
            const unsigned char* mb = (const unsigned char*)mask;
            const int row  = tid >> 1;
            const int half = tid & 1;
            *(uint4*)(Ms + row * BN + half * 16) =
                *(const uint4*)(mb + ((size_t)b * kSQ + q0 + row) * kSK + n0 + half * 16);
        } else if (mode == 1) {
            // int32 0/1
            const int* mi = (const int*)mask;
            #pragma unroll
            for (int i = 0; i < (BM * BN / 4) / NTHREADS; ++i) {   // 4 int4 per thread
                const int idx = tid + i * NTHREADS;                 // 0..511 int4s
                const int row = idx >> 3;                           // 8 int4 per row
                const int c4  = idx & 7;
                int4 v = *(const int4*)(mi + ((size_t)b * kSQ + q0 + row) * kSK + n0 + c4 * 4);
                uchar4 u = make_uchar4(v.x != 0, v.y != 0, v.z != 0, v.w != 0);
                *(uchar4*)(Ms + row * BN + c4 * 4) = u;
            }
        } else {
            // float32 0.0/1.0
            const float* mf = (const float*)mask;
            #pragma unroll
            for (int i = 0; i < (BM * BN / 4) / NTHREADS; ++i) {
                const int idx = tid + i * NTHREADS;
                const int row = idx >> 3;
                const int c4  = idx & 7;
                float4 v = *(const float4*)(mf + ((size_t)b * kSQ + q0 + row) * kSK + n0 + c4 * 4);
                uchar4 u = make_uchar4(v.x != 0.f, v.y != 0.f, v.z != 0.f, v.w != 0.f);
                *(uchar4*)(Ms + row * BN + c4 * 4) = u;
            }
        }

        __syncthreads();

        // ---- S = (0.2 Q) K^T ----
        float s[NT_S][4];
        #pragma unroll
        for (int nt = 0; nt < NT_S; ++nt) { s[nt][0] = 0.f; s[nt][1] = 0.f; s[nt][2] = 0.f; s[nt][3] = 0.f; }
        #pragma unroll
        for (int kt = 0; kt < KT_Q; ++kt) {
            #pragma unroll
            for (int nt = 0; nt < NT_S; ++nt) {
                const uint32_t* kp = &Ks[(nt * 8 + g) * KS_STRIDE + kt * 8 + c];
                mma_tf32(s[nt], qa[kt][0], qa[kt][1], qa[kt][2], qa[kt][3], kp[0], kp[4]);
            }
        }

        // ---- online softmax ----
        float rmax0 = fmaxf(s[0][0], s[0][1]);
        float rmax1 = fmaxf(s[0][2], s[0][3]);
        #pragma unroll
        for (int nt = 1; nt < NT_S; ++nt) {
            rmax0 = fmaxf(rmax0, fmaxf(s[nt][0], s[nt][1]));
            rmax1 = fmaxf(rmax1, fmaxf(s[nt][2], s[nt][3]));
        }
        rmax0 = fmaxf(rmax0, __shfl_xor_sync(0xffffffffu, rmax0, 1));
        rmax0 = fmaxf(rmax0, __shfl_xor_sync(0xffffffffu, rmax0, 2));
        rmax1 = fmaxf(rmax1, __shfl_xor_sync(0xffffffffu, rmax1, 1));
        rmax1 = fmaxf(rmax1, __shfl_xor_sync(0xffffffffu, rmax1, 2));

        const float m0n = fmaxf(m0, rmax0);
        const float m1n = fmaxf(m1, rmax1);
        const float al0 = __expf(m0 - m0n);
        const float al1 = __expf(m1 - m1n);

        float ps0 = 0.f, ps1 = 0.f;
        #pragma unroll
        for (int nt = 0; nt < NT_S; ++nt) {
            const float p0 = __expf(s[nt][0] - m0n);
            const float p1 = __expf(s[nt][1] - m0n);
            const float p2 = __expf(s[nt][2] - m1n);
            const float p3 = __expf(s[nt][3] - m1n);
            ps0 += p0 + p1;                   // UNMASKED sum (reference semantics)
            ps1 += p2 + p3;

            const int col = nt * 8 + 2 * c;
            const unsigned char* mk0 = &Ms[(wrow + g)     * BN + col];
            const unsigned char* mk1 = &Ms[(wrow + g + 8) * BN + col];
            uint2 w0, w1;
            w0.x = f2tf(mk0[0] ? p0 * KEEP_SCALE : 0.f);
            w0.y = f2tf(mk0[1] ? p1 * KEEP_SCALE : 0.f);
            w1.x = f2tf(mk1[0] ? p2 * KEEP_SCALE : 0.f);
            w1.y = f2tf(mk1[1] ? p3 * KEEP_SCALE : 0.f);
            *(uint2*)&Ps[(wrow + g)     * PS_STRIDE + col] = w0;
            *(uint2*)&Ps[(wrow + g + 8) * PS_STRIDE + col] = w1;
        }
        ps0 += __shfl_xor_sync(0xffffffffu, ps0, 1);
        ps0 += __shfl_xor_sync(0xffffffffu, ps0, 2);
        ps1 += __shfl_xor_sync(0xffffffffu, ps1, 1);
        ps1 += __shfl_xor_sync(0xffffffffu, ps1, 2);

        l0 = l0 * al0 + ps0;
        l1 = l1 * al1 + ps1;
        m0 = m0n; m1 = m1n;

        #pragma unroll
        for (int nt = 0; nt < NT_O; ++nt) {
            o[nt][0] *= al0; o[nt][1] *= al0;
            o[nt][2] *= al1; o[nt][3] *= al1;
        }

        __syncwarp();   // P slice is per-warp: STS(P) before cross-lane LDS(P)

        // ---- O += P V ----
        #pragma unroll
        for (int kt = 0; kt < KT_P; ++kt) {
            const uint32_t a0 = Ps[(wrow + g)     * PS_STRIDE + kt * 8 + c];
            const uint32_t a1 = Ps[(wrow + g + 8) * PS_STRIDE + kt * 8 + c];
            const uint32_t a2 = Ps[(wrow + g)     * PS_STRIDE + kt * 8 + c + 4];
            const uint32_t a3 = Ps[(wrow + g + 8) * PS_STRIDE + kt * 8 + c + 4];
            #pragma unroll
            for (int nt = 0; nt < NT_O; ++nt) {
                const uint32_t b0 = Vs[(kt * 8 + c)     * VS_STRIDE + nt * 8 + g];
                const uint32_t b1 = Vs[(kt * 8 + c + 4) * VS_STRIDE + nt * 8 + g];
                mma_tf32(o[nt], a0, a1, a2, a3, b0, b1);
            }
        }
    }

    // ---- epilogue: normalize by UNMASKED denominator and store ----
    const float inv0 = 1.f / l0;
    const float inv1 = 1.f / l1;
    float* ob = O + ((size_t)b * kSQ + q0 + wrow) * kDV;
    #pragma unroll
    for (int nt = 0; nt < NT_O; ++nt) {
        const int col = nt * 8 + 2 * c;
        float2 v0 = make_float2(o[nt][0] * inv0, o[nt][1] * inv0);
        float2 v1 = make_float2(o[nt][2] * inv1, o[nt][3] * inv1);
        *(float2*)(ob + (size_t)g       * kDV + col) = v0;
        *(float2*)(ob + (size_t)(g + 8) * kDV + col) = v1;
    }
}

} // namespace

extern "C" void kernel_launch(void* const* d_in, const int* in_sizes, int n_in,
                              void* d_out, int out_size)
{
    (void)out_size;
    // Identify the mask by its unique element count; the remaining three
    // inputs keep their relative order (x1=Q, x2=K, x3=V) under either
    // dict or alphabetical metadata ordering.
    int midx = 3;
    for (int i = 0; i < n_in; ++i)
        if (in_sizes[i] == MASK_ELEMS) { midx = i; break; }

    const float* qkv[3] = {nullptr, nullptr, nullptr};
    int j = 0;
    for (int i = 0; i < n_in && j < 3; ++i)
        if (i != midx) qkv[j++] = (const float*)d_in[i];

    const void* mask = d_in[midx];
    float* out = (float*)d_out;

    detect_mask_kernel<<<1, 256>>>((const uint32_t*)mask);

    dim3 grid(kSQ / BM, kB);
    fa_tf32_kernel<<<grid, NTHREADS>>>(qkv[0], qkv[1], qkv[2], mask, out);
}

// round 17
// speedup vs baseline: 1.0028x; 1.0001x over previous
#include <cuda_runtime.h>
#include <cstdint>
#include <cmath>

namespace {

constexpr int kB  = 16;
constexpr int kSQ = 2048;
constexpr int kSK = 2048;
constexpr int kD  = 128;
constexpr int kDV = 128;

constexpr int BM = 64;          // query rows per CTA (16 per warp)
constexpr int BN = 32;          // keys per iteration
constexpr int NWARPS = 4;
constexpr int NTHREADS = NWARPS * 32;

constexpr int KT_Q = kD / 8;    // 16 k-tiles for S = Q K^T
constexpr int NT_S = BN / 8;    // 4 n-tiles of S
constexpr int KT_P = BN / 8;    // 4 k-tiles for O += P V
constexpr int NT_O = kDV / 8;   // 16 n-tiles of O

// padded smem strides (in 32-bit words) -> conflict-free fragment reads
constexpr int KS_STRIDE = kD + 4;    // 132
constexpr int VS_STRIDE = kDV + 8;   // 136
constexpr int PS_STRIDE = BN + 4;    // 36

constexpr float INV_SCALE  = 0.2f;          // scores * (1/SCALE_FACTOR)
constexpr float KEEP_SCALE = 1.0f / 0.9f;   // inverted-dropout scale

constexpr int MASK_ELEMS = kB * kSQ * kSK;  // 67,108,864 — unique among inputs

// mask dtype mode: 0 = uint8 bytes, 1 = int32, 2 = float32
__device__ int g_mask_mode;

__global__ void detect_mask_kernel(const uint32_t* __restrict__ m) {
    __shared__ int s_i32, s_f32;
    if (threadIdx.x == 0) { s_i32 = 0; s_f32 = 0; }
    __syncthreads();
    int ci = 0, cf = 0;
    // 16384 samples, stride 997 words: max index 16,334,851 words < 16,777,216
    // (the smallest possible buffer: 67,108,864 bytes if the mask is uint8).
    for (int i = threadIdx.x; i < 16384; i += blockDim.x) {
        uint32_t w = m[(size_t)i * 997u];
        ci += (w <= 1u) ? 1 : 0;
        cf += (w == 0u || w == 0x3F800000u) ? 1 : 0;
    }
    atomicAdd(&s_i32, ci);
    atomicAdd(&s_f32, cf);
    __syncthreads();
    if (threadIdx.x == 0) {
        int mode = 0;                      // default: raw bytes
        if (s_i32 > 16300)      mode = 1;  // words are all 0/1 -> int32
        else if (s_f32 > 16300) mode = 2;  // words are all 0.0f/1.0f -> float32
        g_mask_mode = mode;
    }
}

__device__ __forceinline__ uint32_t f2tf(float f) {
    uint32_t r;
    asm("cvt.rna.tf32.f32 %0, %1;" : "=r"(r) : "f"(f));
    return r;
}

__device__ __forceinline__ void mma_tf32(float* d,
                                         uint32_t a0, uint32_t a1, uint32_t a2, uint32_t a3,
                                         uint32_t b0, uint32_t b1) {
    asm volatile(
        "mma.sync.aligned.m16n8k8.row.col.f32.tf32.tf32.f32 "
        "{%0,%1,%2,%3}, {%4,%5,%6,%7}, {%8,%9}, {%0,%1,%2,%3};\n"
        : "+f"(d[0]), "+f"(d[1]), "+f"(d[2]), "+f"(d[3])
        : "r"(a0), "r"(a1), "r"(a2), "r"(a3), "r"(b0), "r"(b1));
}

__global__ void __launch_bounds__(NTHREADS, 2)
fa_tf32_kernel(const float* __restrict__ Q, const float* __restrict__ K,
               const float* __restrict__ V, const void* __restrict__ mask,
               float* __restrict__ O)
{
    __shared__ __align__(16) uint32_t Ks[BN * KS_STRIDE];   // tf32 K tile [key][d]
    __shared__ __align__(16) uint32_t Vs[BN * VS_STRIDE];   // tf32 V tile [key][dv]
    __shared__ __align__(16) uint32_t Ps[BM * PS_STRIDE];   // tf32 masked probs
    __shared__ __align__(16) unsigned char Ms[BM * BN];     // mask tile (bytes, 1=keep)

    const int tid  = threadIdx.x;
    const int warp = tid >> 5;
    const int lane = tid & 31;
    const int g    = lane >> 2;   // groupID (row within m16 tile)
    const int c    = lane & 3;    // threadID-in-group
    const int b    = blockIdx.y;
    const int q0   = blockIdx.x * BM;
    const int wrow = warp * 16;
    const int mode = g_mask_mode; // uniform across grid

    // ---- Q fragments, resident for the whole kernel; fold 0.2 scale in fp32 ----
    uint32_t qa[KT_Q][4];
    {
        const float* r0p = Q + ((size_t)b * kSQ + q0 + wrow + g) * kD;
        const float* r1p = r0p + 8 * (size_t)kD;
        #pragma unroll
        for (int kt = 0; kt < KT_Q; ++kt) {
            const int cb = kt * 8 + c;
            qa[kt][0] = f2tf(r0p[cb]     * INV_SCALE);
            qa[kt][1] = f2tf(r1p[cb]     * INV_SCALE);
            qa[kt][2] = f2tf(r0p[cb + 4] * INV_SCALE);
            qa[kt][3] = f2tf(r1p[cb + 4] * INV_SCALE);
        }
    }

    float o[NT_O][4];
    #pragma unroll
    for (int nt = 0; nt < NT_O; ++nt) { o[nt][0] = 0.f; o[nt][1] = 0.f; o[nt][2] = 0.f; o[nt][3] = 0.f; }
    float m0 = -INFINITY, m1 = -INFINITY;   // running row maxima (rows g, g+8)
    float l0 = 0.f, l1 = 0.f;               // running UNMASKED softmax denominators

    for (int n0 = 0; n0 < kSK; n0 += BN) {
        __syncthreads();   // previous iteration done reading Ks/Vs/Ms

        // ---- stage K tile (fp32 -> tf32) ----
        {
            const float4* src = (const float4*)(K + ((size_t)b * kSK + n0) * kD);
            #pragma unroll
            for (int i = 0; i < (BN * kD / 4) / NTHREADS; ++i) {
                const int idx = tid + i * NTHREADS;
                const int row = idx >> 5;
                const int c4  = idx & 31;
                float4 v = src[idx];
                uint4 t;
                t.x = f2tf(v.x); t.y = f2tf(v.y); t.z = f2tf(v.z); t.w = f2tf(v.w);
                *(uint4*)&Ks[row * KS_STRIDE + c4 * 4] = t;
            }
        }
        // ---- stage V tile (fp32 -> tf32) ----
        {
            const float4* src = (const float4*)(V + ((size_t)b * kSK + n0) * kDV);
            #pragma unroll
            for (int i = 0; i < (BN * kDV / 4) / NTHREADS; ++i) {
                const int idx = tid + i * NTHREADS;
                const int row = idx >> 5;
                const int c4  = idx & 31;
                float4 v = src[idx];
                uint4 t;
                t.x = f2tf(v.x); t.y = f2tf(v.y); t.z = f2tf(v.z); t.w = f2tf(v.w);
                *(uint4*)&Vs[row * VS_STRIDE + c4 * 4] = t;
            }
        }
        // ---- stage mask tile [BM][BN] -> bytes, dtype-adaptive ----
        if (mode == 0) {
            // raw bytes (bool as uint8)
            const unsigned char* mb = (const unsigned char*)mask;
            const int row  = tid >> 1;
            const int half = tid & 1;
            *(uint4*)(Ms + row * BN + half * 16) =
                *(const uint4*)(mb + ((size_t)b * kSQ + q0 + row) * kSK + n0 + half * 16);
        } else if (mode == 1) {
            // int32 0/1
            const int* mi = (const int*)mask;
            #pragma unroll
            for (int i = 0; i < (BM * BN / 4) / NTHREADS; ++i) {   // 4 int4 per thread
                const int idx = tid + i * NTHREADS;                 // 0..511 int4s
                const int row = idx >> 3;                           // 8 int4 per row
                const int c4  = idx & 7;
                int4 v = *(const int4*)(mi + ((size_t)b * kSQ + q0 + row) * kSK + n0 + c4 * 4);
                uchar4 u = make_uchar4(v.x != 0, v.y != 0, v.z != 0, v.w != 0);
                *(uchar4*)(Ms + row * BN + c4 * 4) = u;
            }
        } else {
            // float32 0.0/1.0
            const float* mf = (const float*)mask;
            #pragma unroll
            for (int i = 0; i < (BM * BN / 4) / NTHREADS; ++i) {
                const int idx = tid + i * NTHREADS;
                const int row = idx >> 3;
                const int c4  = idx & 7;
                float4 v = *(const float4*)(mf + ((size_t)b * kSQ + q0 + row) * kSK + n0 + c4 * 4);
                uchar4 u = make_uchar4(v.x != 0.f, v.y != 0.f, v.z != 0.f, v.w != 0.f);
                *(uchar4*)(Ms + row * BN + c4 * 4) = u;
            }
        }

        __syncthreads();

        // ---- S = (0.2 Q) K^T ----
        float s[NT_S][4];
        #pragma unroll
        for (int nt = 0; nt < NT_S; ++nt) { s[nt][0] = 0.f; s[nt][1] = 0.f; s[nt][2] = 0.f; s[nt][3] = 0.f; }
        #pragma unroll
        for (int kt = 0; kt < KT_Q; ++kt) {
            #pragma unroll
            for (int nt = 0; nt < NT_S; ++nt) {
                const uint32_t* kp = &Ks[(nt * 8 + g) * KS_STRIDE + kt * 8 + c];
                mma_tf32(s[nt], qa[kt][0], qa[kt][1], qa[kt][2], qa[kt][3], kp[0], kp[4]);
            }
        }

        // ---- online softmax ----
        float rmax0 = fmaxf(s[0][0], s[0][1]);
        float rmax1 = fmaxf(s[0][2], s[0][3]);
        #pragma unroll
        for (int nt = 1; nt < NT_S; ++nt) {
            rmax0 = fmaxf(rmax0, fmaxf(s[nt][0], s[nt][1]));
            rmax1 = fmaxf(rmax1, fmaxf(s[nt][2], s[nt][3]));
        }
        rmax0 = fmaxf(rmax0, __shfl_xor_sync(0xffffffffu, rmax0, 1));
        rmax0 = fmaxf(rmax0, __shfl_xor_sync(0xffffffffu, rmax0, 2));
        rmax1 = fmaxf(rmax1, __shfl_xor_sync(0xffffffffu, rmax1, 1));
        rmax1 = fmaxf(rmax1, __shfl_xor_sync(0xffffffffu, rmax1, 2));

        const float m0n = fmaxf(m0, rmax0);
        const float m1n = fmaxf(m1, rmax1);
        const float al0 = __expf(m0 - m0n);
        const float al1 = __expf(m1 - m1n);

        float ps0 = 0.f, ps1 = 0.f;
        #pragma unroll
        for (int nt = 0; nt < NT_S; ++nt) {
            const float p0 = __expf(s[nt][0] - m0n);
            const float p1 = __expf(s[nt][1] - m0n);
            const float p2 = __expf(s[nt][2] - m1n);
            const float p3 = __expf(s[nt][3] - m1n);
            ps0 += p0 + p1;                   // UNMASKED sum (reference semantics)
            ps1 += p2 + p3;

            const int col = nt * 8 + 2 * c;
            const unsigned char* mk0 = &Ms[(wrow + g)     * BN + col];
            const unsigned char* mk1 = &Ms[(wrow + g + 8) * BN + col];
            uint2 w0, w1;
            w0.x = f2tf(mk0[0] ? p0 * KEEP_SCALE : 0.f);
            w0.y = f2tf(mk0[1] ? p1 * KEEP_SCALE : 0.f);
            w1.x = f2tf(mk1[0] ? p2 * KEEP_SCALE : 0.f);
            w1.y = f2tf(mk1[1] ? p3 * KEEP_SCALE : 0.f);
            *(uint2*)&Ps[(wrow + g)     * PS_STRIDE + col] = w0;
            *(uint2*)&Ps[(wrow + g + 8) * PS_STRIDE + col] = w1;
        }
        ps0 += __shfl_xor_sync(0xffffffffu, ps0, 1);
        ps0 += __shfl_xor_sync(0xffffffffu, ps0, 2);
        ps1 += __shfl_xor_sync(0xffffffffu, ps1, 1);
        ps1 += __shfl_xor_sync(0xffffffffu, ps1, 2);

        l0 = l0 * al0 + ps0;
        l1 = l1 * al1 + ps1;
        m0 = m0n; m1 = m1n;

        #pragma unroll
        for (int nt = 0; nt < NT_O; ++nt) {
            o[nt][0] *= al0; o[nt][1] *= al0;
            o[nt][2] *= al1; o[nt][3] *= al1;
        }

        __syncwarp();   // P slice is per-warp: STS(P) before cross-lane LDS(P)

        // ---- O += P V ----
        #pragma unroll
        for (int kt = 0; kt < KT_P; ++kt) {
            const uint32_t a0 = Ps[(wrow + g)     * PS_STRIDE + kt * 8 + c];
            const uint32_t a1 = Ps[(wrow + g + 8) * PS_STRIDE + kt * 8 + c];
            const uint32_t a2 = Ps[(wrow + g)     * PS_STRIDE + kt * 8 + c + 4];
            const uint32_t a3 = Ps[(wrow + g + 8) * PS_STRIDE + kt * 8 + c + 4];
            #pragma unroll
            for (int nt = 0; nt < NT_O; ++nt) {
                const uint32_t b0 = Vs[(kt * 8 + c)     * VS_STRIDE + nt * 8 + g];
                const uint32_t b1 = Vs[(kt * 8 + c + 4) * VS_STRIDE + nt * 8 + g];
                mma_tf32(o[nt], a0, a1, a2, a3, b0, b1);
            }
        }
    }

    // ---- epilogue: normalize by UNMASKED denominator and store ----
    const float inv0 = 1.f / l0;
    const float inv1 = 1.f / l1;
    float* ob = O + ((size_t)b * kSQ + q0 + wrow) * kDV;
    #pragma unroll
    for (int nt = 0; nt < NT_O; ++nt) {
        const int col = nt * 8 + 2 * c;
        float2 v0 = make_float2(o[nt][0] * inv0, o[nt][1] * inv0);
        float2 v1 = make_float2(o[nt][2] * inv1, o[nt][3] * inv1);
        *(float2*)(ob + (size_t)g       * kDV + col) = v0;
        *(float2*)(ob + (size_t)(g + 8) * kDV + col) = v1;
    }
}

} // namespace

extern "C" void kernel_launch(void* const* d_in, const int* in_sizes, int n_in,
                              void* d_out, int out_size)
{
    (void)out_size;
    // Identify the mask by its unique element count; the remaining three
    // inputs keep their relative order (x1=Q, x2=K, x3=V) under either
    // dict or alphabetical metadata ordering.
    int midx = 3;
    for (int i = 0; i < n_in; ++i)
        if (in_sizes[i] == MASK_ELEMS) { midx = i; break; }

    const float* qkv[3] = {nullptr, nullptr, nullptr};
    int j = 0;
    for (int i = 0; i < n_in && j < 3; ++i)
        if (i != midx) qkv[j++] = (const float*)d_in[i];

    const void* mask = d_in[midx];
    float* out = (float*)d_out;

    detect_mask_kernel<<<1, 256>>>((const uint32_t*)mask);

    dim3 grid(kSQ / BM, kB);
    fa_tf32_kernel<<<grid, NTHREADS>>>(qkv[0], qkv[1], qkv[2], mask, out);
}